// round 14
// baseline (speedup 1.0000x reference)
#include <cuda_runtime.h>
#include <math.h>

#define Bb 128
#define Tt 100
#define Ff 64
#define RP 68   // padded row: [0]=halo0, [1..64]=data, [65]=halo0, [66..67]=pad

typedef unsigned long long u64;

// Inter-phase buffers (device globals: allocation-free).
__device__ float g_enc2[(size_t)Tt * Bb * 32 * Ff];       // enc layer1 hidden seq [t][b][ch][pos]
__device__ float g_h1[Bb * 16 * Ff], g_c1[Bb * 16 * Ff];  // enc layer0 final states
__device__ float g_h2[Bb * 32 * Ff], g_c2[Bb * 32 * Ff];  // enc layer1 final states

__device__ __forceinline__ u64 ffma2(u64 a, u64 b, u64 c) {
    u64 d;
    asm("fma.rn.f32x2 %0, %1, %2, %3;" : "=l"(d) : "l"(a), "l"(b), "l"(c));
    return d;
}
__device__ __forceinline__ u64 fadd2(u64 a, u64 b) {
    u64 d;
    asm("add.rn.f32x2 %0, %1, %2;" : "=l"(d) : "l"(a), "l"(b));
    return d;
}
__device__ __forceinline__ u64 dupf(float x) {
    u64 p; unsigned u = __float_as_uint(x);
    asm("mov.b64 %0, {%1, %2};" : "=l"(p) : "r"(u), "r"(u));
    return p;
}
__device__ __forceinline__ float2 unpk(u64 p) {
    float2 r;
    asm("mov.b64 {%0, %1}, %2;" : "=f"(r.x), "=f"(r.y) : "l"(p));
    return r;
}
__device__ __forceinline__ float sigmoidf_(float x) { return 1.0f / (1.0f + expf(-x)); }

// Accumulate gate pairs over nrows rows. Weights: ulonglong2 per (hc,ci,tap):
//   .x = (w_i, w_f)  .y = (w_o, w_g). Inputs duplicated into both f32x2 lanes.
template<int P>
__device__ __forceinline__ void acc_rows(u64* aif, u64* aog,
                                         const float* __restrict__ rows, int nrows,
                                         const ulonglong2* __restrict__ w, int pos0)
{
#pragma unroll 2
    for (int r = 0; r < nrows; ++r) {
        const float* row = rows + r * RP + pos0;   // idx pos0 holds x[pos0-1]
        u64 L[P + 2];
        if constexpr (P == 4) {
            float4 a = *(const float4*)row;
            float2 b = *(const float2*)(row + 4);
            L[0] = dupf(a.x); L[1] = dupf(a.y); L[2] = dupf(a.z); L[3] = dupf(a.w);
            L[4] = dupf(b.x); L[5] = dupf(b.y);
        } else {
            float2 a = *(const float2*)row;
            float2 b = *(const float2*)(row + 2);
            L[0] = dupf(a.x); L[1] = dupf(a.y); L[2] = dupf(b.x); L[3] = dupf(b.y);
        }
        const ulonglong2 w0 = w[0], w1 = w[1], w2 = w[2];
#pragma unroll
        for (int p = 0; p < P; ++p) {
            aif[p] = ffma2(w0.x, L[p],     aif[p]); aog[p] = ffma2(w0.y, L[p],     aog[p]);
            aif[p] = ffma2(w1.x, L[p + 1], aif[p]); aog[p] = ffma2(w1.y, L[p + 1], aog[p]);
            aif[p] = ffma2(w2.x, L[p + 2], aif[p]); aog[p] = ffma2(w2.y, L[p + 2], aog[p]);
        }
        w += 3;
    }
}

template<int P>
__device__ __forceinline__ void store_partial(const u64* aif, const u64* aog,
                                              u64* __restrict__ scr, int base)
{
    u64* s = scr + base * 8;
#pragma unroll
    for (int p = 0; p < P; ++p) { s[p] = aif[p]; s[P + p] = aog[p]; }
}

// half0: add partner partials, apply gates, update c, write h (and optional global).
template<int P, bool WG>
__device__ __forceinline__ void finish(u64* aif, u64* aog, const u64* __restrict__ scr,
                                       int base, float* __restrict__ c,
                                       float* __restrict__ hnxt, int hc, int pos0,
                                       float* __restrict__ gout)
{
    const u64* s = scr + base * 8;
#pragma unroll
    for (int p = 0; p < P; ++p) { aif[p] = fadd2(aif[p], s[p]); aog[p] = fadd2(aog[p], s[P + p]); }
#pragma unroll
    for (int p = 0; p < P; ++p) {
        float2 xif = unpk(aif[p]), xog = unpk(aog[p]);
        float ig = sigmoidf_(xif.x);
        float fg = sigmoidf_(xif.y);
        float og = sigmoidf_(xog.x);
        float gg = tanhf(xog.y);
        float cn = fg * c[p] + ig * gg;
        c[p] = cn;
        float h = og * tanhf(cn);
        hnxt[hc * RP + 1 + pos0 + p] = h;
        if (WG) gout[hc * Ff + pos0 + p] = h;
    }
}

// ---------------- Encoder: enc0 (16h) + enc1 (32h), fused per timestep ----------------
__global__ void __launch_bounds__(1024, 1)
enc_kernel(const float* __restrict__ x,
           const float* __restrict__ w0g, const float* __restrict__ b0g,
           const float* __restrict__ w1g, const float* __restrict__ b1g)
{
    extern __shared__ float sm[];
    u64*   scr  = (u64*)sm;                // 512*8 u64 = 32KB
    float* sw0  = sm + 8192;               // [16][17][3][4]
    float* sb0  = sw0 + 16 * 17 * 12;
    float* sw1  = sb0 + 64;                // [32][48][3][4]
    float* sb1  = sw1 + 32 * 48 * 12;
    float* xrow = sb1 + 128;
    float* h0b  = xrow + RP;               // 2*16*RP
    float* h1b  = h0b + 2 * 16 * RP;       // 2*32*RP

    const int tid = threadIdx.x, b = blockIdx.x;
    const int base = tid & 511, half = tid >> 9;

    for (int i = tid; i < 16 * 17 * 12; i += 1024) {
        int g = i & 3, dk = (i >> 2) % 3, ci = (i / 12) % 17, hc = i / (12 * 17);
        sw0[i] = w0g[((g * 16 + hc) * 17 + ci) * 9 + dk * 3 + 1];
    }
    for (int i = tid; i < 64; i += 1024) sb0[i] = b0g[(i & 3) * 16 + (i >> 2)];
    for (int i = tid; i < 32 * 48 * 12; i += 1024) {
        int g = i & 3, dk = (i >> 2) % 3, ci = (i / 12) % 48, hc = i / (12 * 48);
        sw1[i] = w1g[((g * 32 + hc) * 48 + ci) * 9 + dk * 3 + 1];
    }
    for (int i = tid; i < 128; i += 1024) sb1[i] = b1g[(i & 3) * 32 + (i >> 2)];
    for (int i = tid; i < 2 * 16 * RP; i += 1024) h0b[i] = 0.f;
    for (int i = tid; i < 2 * 32 * RP; i += 1024) h1b[i] = 0.f;
    if (tid == 0) { xrow[0] = 0.f; xrow[65] = 0.f; xrow[66] = 0.f; xrow[67] = 0.f; }
    __syncthreads();

    const int hc0 = base >> 5, pp0 = (base & 31) * 2;   // layer0: P=2, 16 ch
    const int hc1 = base >> 4, pp1 = (base & 15) * 4;   // layer1: P=4, 32 ch
    const ulonglong2 b0v = ((const ulonglong2*)sb0)[hc0];
    const ulonglong2 b1v = ((const ulonglong2*)sb1)[hc1];
    float c0[2] = {0.f, 0.f};
    float c1[4] = {0.f, 0.f, 0.f, 0.f};

    const float* xb = x + (size_t)b * Tt * Ff;
    int cur = 0;
    for (int t = 0; t < Tt; ++t) {
        if (tid < 64) xrow[1 + tid] = xb[t * Ff + tid];
        __syncthreads();                                    // S1

        // ----- enc0 (CTOT=17: 1 input row + 16 h rows); half0: rows 0..8, half1: rows 9..16
        {
            u64 aif[2], aog[2];
            const ulonglong2* w = (const ulonglong2*)sw0 + (size_t)hc0 * 17 * 3;
            const float* h0cur = h0b + cur * 16 * RP;
            if (half == 0) {
                aif[0] = aif[1] = b0v.x; aog[0] = aog[1] = b0v.y;
                acc_rows<2>(aif, aog, xrow, 1, w, pp0);
                acc_rows<2>(aif, aog, h0cur, 8, w + 3, pp0);
            } else {
                aif[0] = aif[1] = 0; aog[0] = aog[1] = 0;
                acc_rows<2>(aif, aog, h0cur + 8 * RP, 8, w + 9 * 3, pp0);
                store_partial<2>(aif, aog, scr, base);
            }
            __syncthreads();                                // S2
            if (half == 0)
                finish<2, false>(aif, aog, scr, base, c0,
                                 h0b + (cur ^ 1) * 16 * RP, hc0, pp0, nullptr);
        }
        __syncthreads();                                    // S3

        // ----- enc1 (CTOT=48: 16 in rows + 32 h rows); half0: rows 0..23, half1: rows 24..47
        {
            u64 aif[4], aog[4];
            const ulonglong2* w = (const ulonglong2*)sw1 + (size_t)hc1 * 48 * 3;
            const float* h0n = h0b + (cur ^ 1) * 16 * RP;
            const float* h1cur = h1b + cur * 32 * RP;
            if (half == 0) {
                aif[0] = aif[1] = aif[2] = aif[3] = b1v.x;
                aog[0] = aog[1] = aog[2] = aog[3] = b1v.y;
                acc_rows<4>(aif, aog, h0n, 16, w, pp1);
                acc_rows<4>(aif, aog, h1cur, 8, w + 16 * 3, pp1);
            } else {
                aif[0] = aif[1] = aif[2] = aif[3] = 0;
                aog[0] = aog[1] = aog[2] = aog[3] = 0;
                acc_rows<4>(aif, aog, h1cur + 8 * RP, 24, w + 24 * 3, pp1);
                store_partial<4>(aif, aog, scr, base);
            }
            __syncthreads();                                // S4
            if (half == 0)
                finish<4, true>(aif, aog, scr, base, c1,
                                h1b + (cur ^ 1) * 32 * RP, hc1, pp1,
                                g_enc2 + ((size_t)t * Bb + b) * 32 * Ff);
        }
        cur ^= 1;
    }
    __syncthreads();
    if (half == 0) {
#pragma unroll
        for (int p = 0; p < 2; ++p) {
            g_h1[((size_t)b * 16 + hc0) * Ff + pp0 + p] = h0b[cur * 16 * RP + hc0 * RP + 1 + pp0 + p];
            g_c1[((size_t)b * 16 + hc0) * Ff + pp0 + p] = c0[p];
        }
#pragma unroll
        for (int p = 0; p < 4; ++p) {
            g_h2[((size_t)b * 32 + hc1) * Ff + pp1 + p] = h1b[cur * 32 * RP + hc1 * RP + 1 + pp1 + p];
            g_c2[((size_t)b * 32 + hc1) * Ff + pp1 + p] = c1[p];
        }
    }
}

// ---------------- Decoder: dec0 (32h) + dec1 (16h) + 1x1 conv, fused per timestep ------
__global__ void __launch_bounds__(1024, 1)
dec_kernel(const float* __restrict__ wd0g, const float* __restrict__ bd0g,
           const float* __restrict__ wd1g, const float* __restrict__ bd1g,
           const float* __restrict__ fcw, const float* __restrict__ fcb,
           float* __restrict__ out)
{
    extern __shared__ float sm[];
    u64*   scr  = (u64*)sm;                // 32KB
    float* swd0 = sm + 8192;               // [32][64][3][4]
    float* sbd0 = swd0 + 32 * 64 * 12;
    float* swd1 = sbd0 + 128;              // [16][48][3][4]
    float* sbd1 = swd1 + 16 * 48 * 12;
    float* inr  = sbd1 + 64;               // 32*RP
    float* hd0b = inr + 32 * RP;           // 2*32*RP
    float* hd1b = hd0b + 2 * 32 * RP;      // 2*16*RP
    float* sfc  = hd1b + 2 * 16 * RP;      // 20

    const int tid = threadIdx.x, b = blockIdx.x;
    const int base = tid & 511, half = tid >> 9;

    for (int i = tid; i < 32 * 64 * 12; i += 1024) {
        int g = i & 3, dk = (i >> 2) % 3, ci = (i / 12) % 64, hc = i / (12 * 64);
        swd0[i] = wd0g[((g * 32 + hc) * 64 + ci) * 9 + dk * 3 + 1];
    }
    for (int i = tid; i < 128; i += 1024) sbd0[i] = bd0g[(i & 3) * 32 + (i >> 2)];
    for (int i = tid; i < 16 * 48 * 12; i += 1024) {
        int g = i & 3, dk = (i >> 2) % 3, ci = (i / 12) % 48, hc = i / (12 * 48);
        swd1[i] = wd1g[((g * 16 + hc) * 48 + ci) * 9 + dk * 3 + 1];
    }
    for (int i = tid; i < 64; i += 1024) sbd1[i] = bd1g[(i & 3) * 16 + (i >> 2)];
    if (tid < 16) sfc[tid] = fcw[tid];
    if (tid == 16) sfc[16] = fcb[0];
    for (int i = tid; i < 32 * RP; i += 1024) inr[i] = 0.f;
    for (int i = tid; i < 2 * 32 * RP; i += 1024) hd0b[i] = 0.f;
    for (int i = tid; i < 2 * 16 * RP; i += 1024) hd1b[i] = 0.f;
    __syncthreads();

    const int hcA = base >> 4, ppA = (base & 15) * 4;   // dec0: P=4, 32 ch
    const int hcB = base >> 5, ppB = (base & 31) * 2;   // dec1: P=2, 16 ch
    const ulonglong2 b0v = ((const ulonglong2*)sbd0)[hcA];
    const ulonglong2 b1v = ((const ulonglong2*)sbd1)[hcB];

    // Decoder initial states = encoder final states (half0 owner-thread fills).
    float cd0[4] = {0, 0, 0, 0}, cd1[2] = {0, 0};
    if (half == 0) {
#pragma unroll
        for (int p = 0; p < 4; ++p) {
            hd0b[hcA * RP + 1 + ppA + p] = g_h2[((size_t)b * 32 + hcA) * Ff + ppA + p];
            cd0[p] = g_c2[((size_t)b * 32 + hcA) * Ff + ppA + p];
        }
#pragma unroll
        for (int p = 0; p < 2; ++p) {
            hd1b[hcB * RP + 1 + ppB + p] = g_h1[((size_t)b * 16 + hcB) * Ff + ppB + p];
            cd1[p] = g_c1[((size_t)b * 16 + hcB) * Ff + ppB + p];
        }
    }

    int cur = 0;
    for (int t = 0; t < Tt; ++t) {
        const float* src = g_enc2 + ((size_t)t * Bb + b) * 32 * Ff;
        for (int i = tid; i < 32 * Ff; i += 1024)
            inr[(i >> 6) * RP + 1 + (i & 63)] = src[i];
        __syncthreads();                                    // S1

        // ----- dec0 (CTOT=64: 32 in rows + 32 h rows); half0: in rows, half1: h rows
        {
            u64 aif[4], aog[4];
            const ulonglong2* w = (const ulonglong2*)swd0 + (size_t)hcA * 64 * 3;
            const float* hcur = hd0b + cur * 32 * RP;
            if (half == 0) {
                aif[0] = aif[1] = aif[2] = aif[3] = b0v.x;
                aog[0] = aog[1] = aog[2] = aog[3] = b0v.y;
                acc_rows<4>(aif, aog, inr, 32, w, ppA);
            } else {
                aif[0] = aif[1] = aif[2] = aif[3] = 0;
                aog[0] = aog[1] = aog[2] = aog[3] = 0;
                acc_rows<4>(aif, aog, hcur, 32, w + 32 * 3, ppA);
                store_partial<4>(aif, aog, scr, base);
            }
            __syncthreads();                                // S2
            if (half == 0)
                finish<4, false>(aif, aog, scr, base, cd0,
                                 hd0b + (cur ^ 1) * 32 * RP, hcA, ppA, nullptr);
        }
        __syncthreads();                                    // S3

        // ----- dec1 (CTOT=48: 32 in rows [hd0nxt] + 16 h rows); half0: rows 0..23, half1: 24..47
        {
            u64 aif[2], aog[2];
            const ulonglong2* w = (const ulonglong2*)swd1 + (size_t)hcB * 48 * 3;
            const float* h0n = hd0b + (cur ^ 1) * 32 * RP;
            const float* hcur = hd1b + cur * 16 * RP;
            if (half == 0) {
                aif[0] = aif[1] = b1v.x; aog[0] = aog[1] = b1v.y;
                acc_rows<2>(aif, aog, h0n, 24, w, ppB);
            } else {
                aif[0] = aif[1] = 0; aog[0] = aog[1] = 0;
                acc_rows<2>(aif, aog, h0n + 24 * RP, 8, w + 24 * 3, ppB);
                acc_rows<2>(aif, aog, hcur, 16, w + 32 * 3, ppB);
                store_partial<2>(aif, aog, scr, base);
            }
            __syncthreads();                                // S4
            if (half == 0)
                finish<2, false>(aif, aog, scr, base, cd1,
                                 hd1b + (cur ^ 1) * 16 * RP, hcB, ppB, nullptr);
        }
        __syncthreads();                                    // S5

        if (tid < 64) {
            float acc = sfc[16];
            const float* hrow = hd1b + (cur ^ 1) * 16 * RP + 1 + tid;
#pragma unroll
            for (int hc = 0; hc < 16; ++hc) acc = fmaf(sfc[hc], hrow[hc * RP], acc);
            out[((size_t)b * Tt + t) * Ff + tid] = acc;
        }
        cur ^= 1;
    }
}

extern "C" void kernel_launch(void* const* d_in, const int* in_sizes, int n_in,
                              void* d_out, int out_size)
{
    const float* x      = (const float*)d_in[0];
    const float* enc_w0 = (const float*)d_in[1];
    const float* enc_b0 = (const float*)d_in[2];
    const float* enc_w1 = (const float*)d_in[3];
    const float* enc_b1 = (const float*)d_in[4];
    const float* dec_w0 = (const float*)d_in[5];
    const float* dec_b0 = (const float*)d_in[6];
    const float* dec_w1 = (const float*)d_in[7];
    const float* dec_b1 = (const float*)d_in[8];
    const float* fc_w   = (const float*)d_in[9];
    const float* fc_b   = (const float*)d_in[10];
    float* out = (float*)d_out;

    const int ENC_SM = (8192 + 16 * 17 * 12 + 64 + 32 * 48 * 12 + 128 + RP
                        + 2 * 16 * RP + 2 * 32 * RP) * 4;
    const int DEC_SM = (8192 + 32 * 64 * 12 + 128 + 16 * 48 * 12 + 64 + 32 * RP
                        + 2 * 32 * RP + 2 * 16 * RP + 20) * 4;

    cudaFuncSetAttribute(enc_kernel, cudaFuncAttributeMaxDynamicSharedMemorySize, ENC_SM);
    cudaFuncSetAttribute(dec_kernel, cudaFuncAttributeMaxDynamicSharedMemorySize, DEC_SM);

    enc_kernel<<<Bb, 1024, ENC_SM>>>(x, enc_w0, enc_b0, enc_w1, enc_b1);
    dec_kernel<<<Bb, 1024, DEC_SM>>>(dec_w0, dec_b0, dec_w1, dec_b1, fc_w, fc_b, out);
}